// round 3
// baseline (speedup 1.0000x reference)
#include <cuda_runtime.h>
#include <cuda_fp16.h>
#include <cstdint>

// ---------------- problem dims ----------------
#define S_DIM 1024
#define B_DIM 64
#define M_TOT 65536           // S*B
#define QK_DIM 1024
#define KK 2048               // concatenated K = 2*QK
#define H_DIM 1024
#define DV_DIM 1024

// ---------------- GEMM tiling ----------------
#define MT 128
#define NT 256
#define KC 32                 // K halfs per stage
#define NSK (KK / KC)         // 64 k-stages
#define ROW_B 80              // smem row pitch bytes: 32 halfs + 8 pad (16B-aligned, conflict-free ldmatrix)
#define A_BYTES (MT * ROW_B)          // 10240
#define B_BYTES (NT * ROW_B)          // 20480
#define STAGE_BYTES (A_BYTES + B_BYTES)  // 30720
#define SMEM_TILES_OFF 4096
#define SMEM_NEED (SMEM_TILES_OFF + 3 * STAGE_BYTES)   // 96256

// ---------------- device scratch (allocation-free) ----------------
__device__ __half g_A[(size_t)M_TOT * KK];    // packed [queries|keys] fp16 (256 MB)
__device__ __half g_W[(size_t)H_DIM * KK];    // packed [W_q|W_k] fp16 (4 MB)
__device__ float  g_part[4 * M_TOT];          // per-N-tile score partials
__device__ float  g_attn[M_TOT];

// ---------------- helpers ----------------
__device__ __forceinline__ uint32_t smem_u32(const void* p) {
    return (uint32_t)__cvta_generic_to_shared(p);
}

__device__ __forceinline__ void mma16816(float* c, const uint32_t* a, uint32_t b0, uint32_t b1) {
    asm volatile(
        "mma.sync.aligned.m16n8k16.row.col.f32.f16.f16.f32 "
        "{%0,%1,%2,%3}, {%4,%5,%6,%7}, {%8,%9}, {%0,%1,%2,%3};"
        : "+f"(c[0]), "+f"(c[1]), "+f"(c[2]), "+f"(c[3])
        : "r"(a[0]), "r"(a[1]), "r"(a[2]), "r"(a[3]), "r"(b0), "r"(b1));
}

__device__ __forceinline__ float fast_tanh(float x) {
    float e = __expf(-2.0f * fabsf(x));          // MUFU.EX2-based, ~1e-7 rel
    float r = __fdividef(1.0f - e, 1.0f + e);    // MUFU.RCP-based
    return copysignf(r, x);
}

// ---------------- Kernel 1: pack [queries|keys] -> fp16 ----------------
__global__ void __launch_bounds__(256) pack_A_kernel(const float4* __restrict__ q,
                                                     const float4* __restrict__ k) {
    const size_t n4 = (size_t)M_TOT * QK_DIM / 4;
    for (size_t i = (size_t)blockIdx.x * blockDim.x + threadIdx.x; i < n4;
         i += (size_t)gridDim.x * blockDim.x) {
        size_t m = i >> 8;               // 256 float4 per QK row
        size_t c = (i & 255) << 2;
        float4 qa = q[i];
        float4 ka = k[i];
        union { __half2 h[2]; uint2 u; } pq, pk;
        pq.h[0] = __floats2half2_rn(qa.x, qa.y);
        pq.h[1] = __floats2half2_rn(qa.z, qa.w);
        pk.h[0] = __floats2half2_rn(ka.x, ka.y);
        pk.h[1] = __floats2half2_rn(ka.z, ka.w);
        *(uint2*)(&g_A[m * KK + c])          = pq.u;
        *(uint2*)(&g_A[m * KK + QK_DIM + c]) = pk.u;
    }
}

// ---------------- Kernel 2: pack [W_q|W_k] -> fp16 ----------------
__global__ void __launch_bounds__(256) pack_W_kernel(const float4* __restrict__ wq,
                                                     const float4* __restrict__ wk) {
    const size_t n4 = (size_t)H_DIM * QK_DIM / 4;
    for (size_t i = (size_t)blockIdx.x * blockDim.x + threadIdx.x; i < n4;
         i += (size_t)gridDim.x * blockDim.x) {
        size_t h = i >> 8;
        size_t c = (i & 255) << 2;
        float4 qa = wq[i];
        float4 ka = wk[i];
        union { __half2 h2[2]; uint2 u; } pq, pk;
        pq.h2[0] = __floats2half2_rn(qa.x, qa.y);
        pq.h2[1] = __floats2half2_rn(qa.z, qa.w);
        pk.h2[0] = __floats2half2_rn(ka.x, ka.y);
        pk.h2[1] = __floats2half2_rn(ka.z, ka.w);
        *(uint2*)(&g_W[h * KK + c])          = pq.u;
        *(uint2*)(&g_W[h * KK + QK_DIM + c]) = pk.u;
    }
}

// ---------------- Kernel 3: GEMM(features) + tanh + w_v reduce -> score partials ----------------
__global__ void __launch_bounds__(512, 1)
gemm_scores_kernel(const float* __restrict__ w_v) {
    extern __shared__ char smem[];
    float* sWv   = (float*)smem;                 // 256 floats
    float* sPart = (float*)(smem + 1024);        // 4*128 floats
    char*  tiles = smem + SMEM_TILES_OFF;

    const int tid  = threadIdx.x;
    const int wid  = tid >> 5;
    const int lane = tid & 31;
    const int wm   = wid & 3;        // warp m index (0..3) -> 32 rows each
    const int wn   = wid >> 2;       // warp n index (0..3) -> 64 cols each
    const int nt   = blockIdx.x;     // N tile (0..3), fastest varying for L2 reuse of A
    const int m0   = blockIdx.y * MT;
    const int h0   = nt * NT;

    if (tid < 256) sWv[tid] = w_v[h0 + tid];

    float acc[2][8][4];
#pragma unroll
    for (int mf = 0; mf < 2; mf++)
#pragma unroll
        for (int nf = 0; nf < 8; nf++)
#pragma unroll
            for (int i = 0; i < 4; i++) acc[mf][nf][i] = 0.f;

    // ---- cp.async stage loader: A tile 128x32, B tile 256x32 halfs ----
    auto issue_stage = [&](int buf, int k0) {
        char* As = tiles + buf * STAGE_BYTES;
        char* Bs = As + A_BYTES;
        {
            int r = tid >> 2, c = tid & 3;   // 512 chunks of 16B
            uint32_t sa = smem_u32(As + r * ROW_B + c * 16);
            size_t ga = (size_t)__cvta_generic_to_global(
                g_A + (size_t)(m0 + r) * KK + k0 + c * 8);
            asm volatile("cp.async.cg.shared.global [%0], [%1], 16;" :: "r"(sa), "l"(ga));
        }
#pragma unroll
        for (int j = 0; j < 2; j++) {        // 1024 chunks of 16B
            int i = tid + j * 512;
            int r = i >> 2, c = i & 3;
            uint32_t sb = smem_u32(Bs + r * ROW_B + c * 16);
            size_t gb = (size_t)__cvta_generic_to_global(
                g_W + (size_t)(h0 + r) * KK + k0 + c * 8);
            asm volatile("cp.async.cg.shared.global [%0], [%1], 16;" :: "r"(sb), "l"(gb));
        }
        asm volatile("cp.async.commit_group;" ::: "memory");
    };

    auto compute_stage = [&](int buf) {
        char* As = tiles + buf * STAGE_BYTES;
        char* Bs = As + A_BYTES;
#pragma unroll
        for (int ks = 0; ks < 2; ks++) {     // two k16 steps per 32-half stage
            uint32_t a[2][4];
#pragma unroll
            for (int mf = 0; mf < 2; mf++) {
                int row = wm * 32 + mf * 16 + (lane & 7) + (lane & 8);
                int kb  = ks * 32 + ((lane >= 16) ? 16 : 0);
                uint32_t addr = smem_u32(As + row * ROW_B + kb);
                asm volatile(
                    "ldmatrix.sync.aligned.m8n8.x4.shared.b16 {%0,%1,%2,%3}, [%4];"
                    : "=r"(a[mf][0]), "=r"(a[mf][1]), "=r"(a[mf][2]), "=r"(a[mf][3])
                    : "r"(addr));
            }
#pragma unroll
            for (int np = 0; np < 4; np++) { // each x4 covers 2 n-frags
                uint32_t b[4];
                int rn = wn * 64 + np * 16 + (lane & 7) + ((lane >= 16) ? 8 : 0);
                int kb = ks * 32 + ((lane & 8) ? 16 : 0);
                uint32_t addr = smem_u32(Bs + rn * ROW_B + kb);
                asm volatile(
                    "ldmatrix.sync.aligned.m8n8.x4.shared.b16 {%0,%1,%2,%3}, [%4];"
                    : "=r"(b[0]), "=r"(b[1]), "=r"(b[2]), "=r"(b[3])
                    : "r"(addr));
#pragma unroll
                for (int mf = 0; mf < 2; mf++) {
                    mma16816(acc[mf][2 * np],     a[mf], b[0], b[1]);
                    mma16816(acc[mf][2 * np + 1], a[mf], b[2], b[3]);
                }
            }
        }
    };

    // ---- 3-stage pipeline ----
    issue_stage(0, 0);
    issue_stage(1, KC);
    for (int s = 0; s < NSK; s++) {
        if (s == NSK - 1) { asm volatile("cp.async.wait_group 0;" ::: "memory"); }
        else              { asm volatile("cp.async.wait_group 1;" ::: "memory"); }
        __syncthreads();
        if (s + 2 < NSK) issue_stage((s + 2) % 3, (s + 2) * KC);
        compute_stage(s % 3);
    }

    // ---- epilogue: score_partial[m] = sum_h tanh(feat[m,h]) * w_v[h] ----
    float s0[2] = {0.f, 0.f}, s1[2] = {0.f, 0.f};
#pragma unroll
    for (int mf = 0; mf < 2; mf++) {
#pragma unroll
        for (int nf = 0; nf < 8; nf++) {
            int colb = wn * 64 + nf * 8 + 2 * (lane & 3);
            float wv0 = sWv[colb], wv1 = sWv[colb + 1];
            s0[mf] += fast_tanh(acc[mf][nf][0]) * wv0 + fast_tanh(acc[mf][nf][1]) * wv1;
            s1[mf] += fast_tanh(acc[mf][nf][2]) * wv0 + fast_tanh(acc[mf][nf][3]) * wv1;
        }
    }
#pragma unroll
    for (int mf = 0; mf < 2; mf++) {
#pragma unroll
        for (int o = 1; o <= 2; o <<= 1) {
            s0[mf] += __shfl_xor_sync(0xFFFFFFFFu, s0[mf], o);
            s1[mf] += __shfl_xor_sync(0xFFFFFFFFu, s1[mf], o);
        }
    }
    __syncthreads();   // tiles no longer needed; protect sPart region ordering
    if ((lane & 3) == 0) {
#pragma unroll
        for (int mf = 0; mf < 2; mf++) {
            int r = wm * 32 + mf * 16 + (lane >> 2);
            sPart[wn * 128 + r]     = s0[mf];
            sPart[wn * 128 + r + 8] = s1[mf];
        }
    }
    __syncthreads();
    if (tid < 128) {
        float tot = sPart[tid] + sPart[128 + tid] + sPart[256 + tid] + sPart[384 + tid];
        g_part[nt * M_TOT + m0 + tid] = tot;
    }
}

// ---------------- Kernel 4: softmax over S (per b column) ----------------
__global__ void __launch_bounds__(256) softmax_kernel() {
    int b = blockIdx.x, t = threadIdx.x;
    int wid = t >> 5, lid = t & 31;
    __shared__ float sm1[8], sm2[8];
    float v[4];
    float mx = -1e30f;
#pragma unroll
    for (int j = 0; j < 4; j++) {
        int m = (j * 256 + t) * B_DIM + b;
        v[j] = g_part[m] + g_part[M_TOT + m] + g_part[2 * M_TOT + m] + g_part[3 * M_TOT + m];
        mx = fmaxf(mx, v[j]);
    }
#pragma unroll
    for (int o = 16; o; o >>= 1) mx = fmaxf(mx, __shfl_xor_sync(0xFFFFFFFFu, mx, o));
    if (lid == 0) sm1[wid] = mx;
    __syncthreads();
    mx = sm1[0];
#pragma unroll
    for (int w = 1; w < 8; w++) mx = fmaxf(mx, sm1[w]);

    float e[4];
    float sum = 0.f;
#pragma unroll
    for (int j = 0; j < 4; j++) { e[j] = __expf(v[j] - mx); sum += e[j]; }
#pragma unroll
    for (int o = 16; o; o >>= 1) sum += __shfl_xor_sync(0xFFFFFFFFu, sum, o);
    if (lid == 0) sm2[wid] = sum;
    __syncthreads();
    sum = 0.f;
#pragma unroll
    for (int w = 0; w < 8; w++) sum += sm2[w];
    float inv = 1.0f / sum;
#pragma unroll
    for (int j = 0; j < 4; j++)
        g_attn[(size_t)(j * 256 + t) * B_DIM + b] = e[j] * inv;
}

// ---------------- Kernel 5: out[b,d] = sum_s attn[s,b] * values[s,d] ----------------
__global__ void __launch_bounds__(1024) output_kernel(const float* __restrict__ values,
                                                      float* __restrict__ out) {
    __shared__ float sa[128 * 64];   // attn chunk (32 KB)
    __shared__ float sv[128 * 16];   // values chunk (8 KB)
    int t = threadIdx.x;
    int d0 = blockIdx.x * 16;
    int b = t >> 4, dd = t & 15;
    float acc = 0.f;
    for (int sc = 0; sc < 8; sc++) {
        __syncthreads();
#pragma unroll
        for (int j = 0; j < 8; j++) {
            int i = t + j * 1024;
            sa[i] = g_attn[(size_t)sc * 8192 + i];
        }
#pragma unroll
        for (int j = 0; j < 2; j++) {
            int i = t + j * 1024;
            int sr = i >> 4, c = i & 15;
            sv[i] = values[(size_t)(sc * 128 + sr) * DV_DIM + d0 + c];
        }
        __syncthreads();
#pragma unroll 8
        for (int s = 0; s < 128; s++)
            acc += sa[s * 64 + b] * sv[s * 16 + dd];
    }
    out[(size_t)b * DV_DIM + d0 + dd] = acc;
}

// ---------------- launch ----------------
extern "C" void kernel_launch(void* const* d_in, const int* in_sizes, int n_in,
                              void* d_out, int out_size) {
    const float* queries = (const float*)d_in[0];
    const float* keys    = (const float*)d_in[1];
    const float* values  = (const float*)d_in[2];
    const float* W_q     = (const float*)d_in[3];
    const float* W_k     = (const float*)d_in[4];
    const float* w_v     = (const float*)d_in[5];
    float* out = (float*)d_out;

    static bool attr_set = false;
    if (!attr_set) {
        cudaFuncSetAttribute(gemm_scores_kernel,
                             cudaFuncAttributeMaxDynamicSharedMemorySize, SMEM_NEED);
        attr_set = true;
    }

    pack_A_kernel<<<2048, 256>>>((const float4*)queries, (const float4*)keys);
    pack_W_kernel<<<256, 256>>>((const float4*)W_q, (const float4*)W_k);
    gemm_scores_kernel<<<dim3(4, M_TOT / MT), 512, SMEM_NEED>>>(w_v);
    softmax_kernel<<<B_DIM, 256>>>();
    output_kernel<<<DV_DIM / 16, 1024>>>(values, out);
}

// round 4
// speedup vs baseline: 1.2144x; 1.2144x over previous
#include <cuda_runtime.h>
#include <cuda_fp16.h>
#include <cstdint>

// ---------------- problem dims ----------------
#define S_DIM 1024
#define B_DIM 64
#define M_TOT 65536           // S*B
#define QK_DIM 1024
#define KK 2048               // concatenated K = 2*QK
#define H_DIM 1024
#define DV_DIM 1024

// ---------------- GEMM tiling ----------------
#define MT 128
#define NT 256
#define KC 64                 // K halfs per stage
#define NSK (KK / KC)         // 32 k-stages
#define ROW_B 144             // smem row pitch bytes: 64 halfs + 8 pad halfs
#define A_BYTES (MT * ROW_B)             // 18432
#define B_BYTES (NT * ROW_B)             // 36864
#define STAGE_BYTES (A_BYTES + B_BYTES)  // 55296
#define SMEM_TILES_OFF 4096
#define SMEM_NEED (SMEM_TILES_OFF + 3 * STAGE_BYTES)   // 169984

// ---------------- device scratch (allocation-free) ----------------
__device__ __half g_W[(size_t)H_DIM * KK];    // packed [W_q|W_k] fp16 (4 MB)
__device__ float  g_part[4 * M_TOT];          // per-N-tile score partials
__device__ float  g_attn[M_TOT];

// ---------------- helpers ----------------
__device__ __forceinline__ uint32_t smem_u32(const void* p) {
    return (uint32_t)__cvta_generic_to_shared(p);
}

__device__ __forceinline__ void mma16816(float* c, const uint32_t* a, uint32_t b0, uint32_t b1) {
    asm volatile(
        "mma.sync.aligned.m16n8k16.row.col.f32.f16.f16.f32 "
        "{%0,%1,%2,%3}, {%4,%5,%6,%7}, {%8,%9}, {%0,%1,%2,%3};"
        : "+f"(c[0]), "+f"(c[1]), "+f"(c[2]), "+f"(c[3])
        : "r"(a[0]), "r"(a[1]), "r"(a[2]), "r"(a[3]), "r"(b0), "r"(b1));
}

__device__ __forceinline__ float fast_tanh(float x) {
    float e = __expf(-2.0f * fabsf(x));          // MUFU.EX2-based, ~1e-7 rel
    float r = __fdividef(1.0f - e, 1.0f + e);    // MUFU.RCP-based
    return copysignf(r, x);
}

// ---------------- Kernel 1: pack [W_q|W_k] -> fp16 ----------------
__global__ void __launch_bounds__(256) pack_W_kernel(const float4* __restrict__ wq,
                                                     const float4* __restrict__ wk) {
    const size_t n4 = (size_t)H_DIM * QK_DIM / 4;
    for (size_t i = (size_t)blockIdx.x * blockDim.x + threadIdx.x; i < n4;
         i += (size_t)gridDim.x * blockDim.x) {
        size_t h = i >> 8;
        size_t c = (i & 255) << 2;
        float4 qa = wq[i];
        float4 ka = wk[i];
        union { __half2 h2[2]; uint2 u; } pq, pk;
        pq.h2[0] = __floats2half2_rn(qa.x, qa.y);
        pq.h2[1] = __floats2half2_rn(qa.z, qa.w);
        pk.h2[0] = __floats2half2_rn(ka.x, ka.y);
        pk.h2[1] = __floats2half2_rn(ka.z, ka.w);
        *(uint2*)(&g_W[h * KK + c])          = pq.u;
        *(uint2*)(&g_W[h * KK + QK_DIM + c]) = pk.u;
    }
}

// ---------------- Kernel 2: GEMM(features) + tanh + w_v reduce -> score partials ----------------
// A[m, k] (fp32, read directly): k<1024 -> queries[m,k], k>=1024 -> keys[m,k-1024]
__global__ void __launch_bounds__(512, 1)
gemm_scores_kernel(const float* __restrict__ queries,
                   const float* __restrict__ keys,
                   const float* __restrict__ w_v) {
    extern __shared__ char smem[];
    float* sWv   = (float*)smem;                 // 256 floats
    float* sPart = (float*)(smem + 1024);        // 4*128 floats
    char*  tiles = smem + SMEM_TILES_OFF;

    const int tid  = threadIdx.x;
    const int wid  = tid >> 5;
    const int lane = tid & 31;
    const int wm   = wid & 3;        // warp m index (0..3) -> 32 rows each
    const int wn   = wid >> 2;       // warp n index (0..3) -> 64 cols each
    const int nt   = blockIdx.x;     // N tile (0..3), fastest varying: A reuse in L2
    const int m0   = blockIdx.y * MT;
    const int h0   = nt * NT;

    if (tid < 256) sWv[tid] = w_v[h0 + tid];

    float acc[2][8][4];
#pragma unroll
    for (int mf = 0; mf < 2; mf++)
#pragma unroll
        for (int nf = 0; nf < 8; nf++)
#pragma unroll
            for (int i = 0; i < 4; i++) acc[mf][nf][i] = 0.f;

    // per-thread A-chunk mapping: i = tid + j*512 (j=0..3), r = i>>4, c = i&15
    const int ar = tid >> 4;              // base row for j=0; rows step by 32 per j
    const int ac = tid & 15;              // float4 col within 64-float k-chunk

    float4 pre[4];

    // LDG fp32 A for stage s into pre[]
    auto ldg_A = [&](int s) {
        const int kc = (s < 16) ? s * KC : (s - 16) * KC;
        const float* src = (s < 16) ? queries : keys;
#pragma unroll
        for (int j = 0; j < 4; j++) {
            int r = ar + j * 32;
            pre[j] = *(const float4*)(src + (size_t)(m0 + r) * QK_DIM + kc + ac * 4);
        }
    };
    // convert pre[] -> fp16 and store to smem buffer
    auto sts_A = [&](int buf) {
        char* As = tiles + buf * STAGE_BYTES;
#pragma unroll
        for (int j = 0; j < 4; j++) {
            int r = ar + j * 32;
            union { __half2 h2[2]; uint2 u; } p;
            p.h2[0] = __floats2half2_rn(pre[j].x, pre[j].y);
            p.h2[1] = __floats2half2_rn(pre[j].z, pre[j].w);
            *(uint2*)(As + r * ROW_B + ac * 8) = p.u;
        }
    };
    // cp.async B tile for stage s: 256 rows x 128 bytes
    auto cp_B = [&](int s, int buf) {
        char* Bs = tiles + buf * STAGE_BYTES + A_BYTES;
        const int k0 = s * KC;
#pragma unroll
        for (int j = 0; j < 4; j++) {
            int i = tid + j * 512;
            int r = i >> 3, c = i & 7;
            uint32_t sb = smem_u32(Bs + r * ROW_B + c * 16);
            size_t gb = (size_t)__cvta_generic_to_global(
                g_W + (size_t)(h0 + r) * KK + k0 + c * 8);
            asm volatile("cp.async.cg.shared.global [%0], [%1], 16;" :: "r"(sb), "l"(gb));
        }
        asm volatile("cp.async.commit_group;" ::: "memory");
    };

    auto compute_stage = [&](int buf) {
        char* As = tiles + buf * STAGE_BYTES;
        char* Bs = As + A_BYTES;
#pragma unroll
        for (int ks = 0; ks < 4; ks++) {     // four k16 steps per 64-half stage
            uint32_t a[2][4];
#pragma unroll
            for (int mf = 0; mf < 2; mf++) {
                int row = wm * 32 + mf * 16 + (lane & 7) + (lane & 8);
                int kb  = ks * 32 + ((lane >= 16) ? 16 : 0);
                uint32_t addr = smem_u32(As + row * ROW_B + kb);
                asm volatile(
                    "ldmatrix.sync.aligned.m8n8.x4.shared.b16 {%0,%1,%2,%3}, [%4];"
                    : "=r"(a[mf][0]), "=r"(a[mf][1]), "=r"(a[mf][2]), "=r"(a[mf][3])
                    : "r"(addr));
            }
#pragma unroll
            for (int np = 0; np < 4; np++) { // each x4 covers 2 n-frags
                uint32_t b[4];
                int rn = wn * 64 + np * 16 + (lane & 7) + ((lane >= 16) ? 8 : 0);
                int kb = ks * 32 + ((lane & 8) ? 16 : 0);
                uint32_t addr = smem_u32(Bs + rn * ROW_B + kb);
                asm volatile(
                    "ldmatrix.sync.aligned.m8n8.x4.shared.b16 {%0,%1,%2,%3}, [%4];"
                    : "=r"(b[0]), "=r"(b[1]), "=r"(b[2]), "=r"(b[3])
                    : "r"(addr));
#pragma unroll
                for (int mf = 0; mf < 2; mf++) {
                    mma16816(acc[mf][2 * np],     a[mf], b[0], b[1]);
                    mma16816(acc[mf][2 * np + 1], a[mf], b[2], b[3]);
                }
            }
        }
    };

    // ---- prologue: stages 0,1 in smem; stage 2 in registers ----
    ldg_A(0); sts_A(0); cp_B(0, 0);
    ldg_A(1); sts_A(1); cp_B(1, 1);
    ldg_A(2);

    // ---- main pipeline ----
    for (int s = 0; s < NSK; s++) {
        if (s == NSK - 1) { asm volatile("cp.async.wait_group 0;" ::: "memory"); }
        else              { asm volatile("cp.async.wait_group 1;" ::: "memory"); }
        __syncthreads();
        if (s + 2 < NSK) {
            int buf = (s + 2) % 3;
            sts_A(buf);
            cp_B(s + 2, buf);
            if (s + 3 < NSK) ldg_A(s + 3);
        }
        compute_stage(s % 3);
    }

    // ---- epilogue: score_partial[m] = sum_h tanh(feat[m,h]) * w_v[h] ----
    float s0[2] = {0.f, 0.f}, s1[2] = {0.f, 0.f};
#pragma unroll
    for (int mf = 0; mf < 2; mf++) {
#pragma unroll
        for (int nf = 0; nf < 8; nf++) {
            int colb = wn * 64 + nf * 8 + 2 * (lane & 3);
            float wv0 = sWv[colb], wv1 = sWv[colb + 1];
            s0[mf] += fast_tanh(acc[mf][nf][0]) * wv0 + fast_tanh(acc[mf][nf][1]) * wv1;
            s1[mf] += fast_tanh(acc[mf][nf][2]) * wv0 + fast_tanh(acc[mf][nf][3]) * wv1;
        }
    }
#pragma unroll
    for (int mf = 0; mf < 2; mf++) {
#pragma unroll
        for (int o = 1; o <= 2; o <<= 1) {
            s0[mf] += __shfl_xor_sync(0xFFFFFFFFu, s0[mf], o);
            s1[mf] += __shfl_xor_sync(0xFFFFFFFFu, s1[mf], o);
        }
    }
    __syncthreads();
    if ((lane & 3) == 0) {
#pragma unroll
        for (int mf = 0; mf < 2; mf++) {
            int r = wm * 32 + mf * 16 + (lane >> 2);
            sPart[wn * 128 + r]     = s0[mf];
            sPart[wn * 128 + r + 8] = s1[mf];
        }
    }
    __syncthreads();
    if (tid < 128) {
        float tot = sPart[tid] + sPart[128 + tid] + sPart[256 + tid] + sPart[384 + tid];
        g_part[nt * M_TOT + m0 + tid] = tot;
    }
}

// ---------------- Kernel 3: softmax over S (per b column) ----------------
__global__ void __launch_bounds__(256) softmax_kernel() {
    int b = blockIdx.x, t = threadIdx.x;
    int wid = t >> 5, lid = t & 31;
    __shared__ float sm1[8], sm2[8];
    float v[4];
    float mx = -1e30f;
#pragma unroll
    for (int j = 0; j < 4; j++) {
        int m = (j * 256 + t) * B_DIM + b;
        v[j] = g_part[m] + g_part[M_TOT + m] + g_part[2 * M_TOT + m] + g_part[3 * M_TOT + m];
        mx = fmaxf(mx, v[j]);
    }
#pragma unroll
    for (int o = 16; o; o >>= 1) mx = fmaxf(mx, __shfl_xor_sync(0xFFFFFFFFu, mx, o));
    if (lid == 0) sm1[wid] = mx;
    __syncthreads();
    mx = sm1[0];
#pragma unroll
    for (int w = 1; w < 8; w++) mx = fmaxf(mx, sm1[w]);

    float e[4];
    float sum = 0.f;
#pragma unroll
    for (int j = 0; j < 4; j++) { e[j] = __expf(v[j] - mx); sum += e[j]; }
#pragma unroll
    for (int o = 16; o; o >>= 1) sum += __shfl_xor_sync(0xFFFFFFFFu, sum, o);
    if (lid == 0) sm2[wid] = sum;
    __syncthreads();
    sum = 0.f;
#pragma unroll
    for (int w = 0; w < 8; w++) sum += sm2[w];
    float inv = 1.0f / sum;
#pragma unroll
    for (int j = 0; j < 4; j++)
        g_attn[(size_t)(j * 256 + t) * B_DIM + b] = e[j] * inv;
}

// ---------------- Kernel 4: out[b,d] = sum_s attn[s,b] * values[s,d] ----------------
__global__ void __launch_bounds__(1024) output_kernel(const float* __restrict__ values,
                                                      float* __restrict__ out) {
    __shared__ float sa[128 * 64];   // attn chunk (32 KB)
    __shared__ float sv[128 * 16];   // values chunk (8 KB)
    int t = threadIdx.x;
    int d0 = blockIdx.x * 16;
    int b = t >> 4, dd = t & 15;
    float acc = 0.f;
    for (int sc = 0; sc < 8; sc++) {
        __syncthreads();
#pragma unroll
        for (int j = 0; j < 8; j++) {
            int i = t + j * 1024;
            sa[i] = g_attn[(size_t)sc * 8192 + i];
        }
#pragma unroll
        for (int j = 0; j < 2; j++) {
            int i = t + j * 1024;
            int sr = i >> 4, c = i & 15;
            sv[i] = values[(size_t)(sc * 128 + sr) * DV_DIM + d0 + c];
        }
        __syncthreads();
#pragma unroll 8
        for (int s = 0; s < 128; s++)
            acc += sa[s * 64 + b] * sv[s * 16 + dd];
    }
    out[(size_t)b * DV_DIM + d0 + dd] = acc;
}

// ---------------- launch ----------------
extern "C" void kernel_launch(void* const* d_in, const int* in_sizes, int n_in,
                              void* d_out, int out_size) {
    const float* queries = (const float*)d_in[0];
    const float* keys    = (const float*)d_in[1];
    const float* values  = (const float*)d_in[2];
    const float* W_q     = (const float*)d_in[3];
    const float* W_k     = (const float*)d_in[4];
    const float* w_v     = (const float*)d_in[5];
    float* out = (float*)d_out;

    cudaFuncSetAttribute(gemm_scores_kernel,
                         cudaFuncAttributeMaxDynamicSharedMemorySize, SMEM_NEED);

    pack_W_kernel<<<256, 256>>>((const float4*)W_q, (const float4*)W_k);
    gemm_scores_kernel<<<dim3(4, M_TOT / MT), 512, SMEM_NEED>>>(queries, keys, w_v);
    softmax_kernel<<<B_DIM, 256>>>();
    output_kernel<<<DV_DIM / 16, 1024>>>(values, out);
}